// round 14
// baseline (speedup 1.0000x reference)
#include <cuda_runtime.h>
#include <cuda_fp16.h>
#include <math.h>
#include <stdint.h>

// Problem constants
#define T_TOK   2048
#define D_MODEL 1024
#define N_EXP   8
#define HIDDEN  4096
#define TOPK    2
#define CAP     2048

// ---------------- scratch (device globals; no dynamic allocation) ----------
__device__ int    g_counts[N_EXP];
__device__ int    g_tok_expert[T_TOK * TOPK];
__device__ int    g_tok_slot[T_TOK * TOPK];
__device__ float  g_tok_weight[T_TOK * TOPK];
__device__ __align__(16) __half g_xg[(size_t)N_EXP * CAP * D_MODEL];  // 32 MB
__device__ __align__(16) __half g_h [(size_t)N_EXP * CAP * HIDDEN];   // 128 MB
__device__ __align__(16) float  g_eo[(size_t)N_EXP * CAP * D_MODEL];  // 64 MB

// ---------------- kernel 0: zero counters (prewarm only) -------------------
__global__ void zero_counts_kernel() {
    if (threadIdx.x < N_EXP) g_counts[threadIdx.x] = 0;
}

__device__ __forceinline__ uint32_t pack_h2(float x, float y) {
    __half2 h = __floats2half2_rn(x, y);
    return *(uint32_t*)&h;
}
__device__ __forceinline__ uint32_t smem_u32(const void* p) {
    uint32_t a;
    asm("{ .reg .u64 t; cvta.to.shared.u64 t, %1; cvt.u32.u64 %0, t; }" : "=r"(a) : "l"(p));
    return a;
}
__device__ __forceinline__ void ldm_x4(uint32_t* r, uint32_t addr) {
    asm volatile("ldmatrix.sync.aligned.m8n8.x4.shared.b16 {%0,%1,%2,%3}, [%4];"
        : "=r"(r[0]), "=r"(r[1]), "=r"(r[2]), "=r"(r[3]) : "r"(addr));
}

// ---------------- kernel 1: routing (R12-proven: one block per token) ------
// No dynamically-indexed local arrays (lmem-pool guard).
__global__ void routing_kernel(const float* __restrict__ x,
                               const float* __restrict__ gate_w) {
    int t = blockIdx.x, tid = threadIdx.x, w = tid >> 5, lane = tid & 31;
    const float* xt = x + (size_t)t * D_MODEL;
    const float* gw = gate_w + (size_t)w * D_MODEL;
    float s = 0.f;
    #pragma unroll 4
    for (int k = lane; k < D_MODEL; k += 32) s += xt[k] * gw[k];
    #pragma unroll
    for (int off = 16; off; off >>= 1) s += __shfl_xor_sync(0xffffffffu, s, off);

    __shared__ float logits[N_EXP];
    __shared__ int   sh_e[TOPK];
    __shared__ int   sh_s[TOPK];
    if (lane == 0) logits[w] = s;
    __syncthreads();

    if (tid == 0) {
        float mx = logits[0];
        #pragma unroll
        for (int i = 1; i < N_EXP; i++) mx = fmaxf(mx, logits[i]);
        float denom = 0.f;
        #pragma unroll
        for (int i = 0; i < N_EXP; i++) denom += expf(logits[i] - mx);
        // top-2 scan; strict '>' keeps lower index on ties (matches jax top_k)
        float v0 = -3.4e38f, v1 = -3.4e38f;
        int   i0 = 0,        i1 = 0;
        #pragma unroll
        for (int i = 0; i < N_EXP; i++) {
            float v = logits[i];
            if (v > v0)      { v1 = v0; i1 = i0; v0 = v; i0 = i; }
            else if (v > v1) { v1 = v;  i1 = i; }
        }
        float p0 = expf(v0 - mx) / denom;
        float p1 = expf(v1 - mx) / denom;
        float inv = 1.f / (p0 + p1);
        p0 *= inv; p1 *= inv;
        int s0 = atomicAdd(&g_counts[i0], 1);
        int s1 = atomicAdd(&g_counts[i1], 1);
        g_tok_expert[t * 2 + 0] = i0;  g_tok_slot[t * 2 + 0] = s0;  g_tok_weight[t * 2 + 0] = p0;
        g_tok_expert[t * 2 + 1] = i1;  g_tok_slot[t * 2 + 1] = s1;  g_tok_weight[t * 2 + 1] = p1;
        sh_e[0] = i0; sh_s[0] = s0; sh_e[1] = i1; sh_s[1] = s1;
    }
    __syncthreads();

    // gather token row (fp32 -> fp16) into both experts' input buffers
    float4 v = ((const float4*)xt)[tid];
    uint2 hv = make_uint2(pack_h2(v.x, v.y), pack_h2(v.z, v.w));
    #pragma unroll
    for (int kk = 0; kk < TOPK; kk++) {
        uint2* dst = (uint2*)(g_xg + ((size_t)sh_e[kk] * CAP + sh_s[kk]) * D_MODEL);
        dst[tid] = hv;
    }
}

// ---------------- fp16 tensor-core grouped NT GEMM, BK=64 ------------------
// C[m,n] = sum_k A[m,k]*B[n,k] + bias[n] (optional ReLU)
// R12 core (proven 333.8us) with the k-tile doubled to 64: HALF the
// __syncthreads / double-buffer overhead per CTA. Dynamic smem (72 KB).
// Stride 72 halves (144 B = 9 x 16B banks): ldmatrix phases and STS remain
// conflict-free ((9r + c) mod 8 is a permutation).

#define BM 128
#define BN 128
#define BK 64
#define BKH 72                       // half stride (144 B)
#define ASZ (BM * BKH)               // halves per A buffer
#define SMEM_BYTES (4 * ASZ * 2)     // 2 bufs x (A + B) = 73728 B

__device__ __forceinline__ void mma_f16(float* c, const uint32_t* a, const uint32_t* b) {
    asm volatile(
        "mma.sync.aligned.m16n8k16.row.col.f32.f16.f16.f32 "
        "{%0,%1,%2,%3}, {%4,%5,%6,%7}, {%8,%9}, {%0,%1,%2,%3};"
        : "+f"(c[0]), "+f"(c[1]), "+f"(c[2]), "+f"(c[3])
        : "r"(a[0]), "r"(a[1]), "r"(a[2]), "r"(a[3]), "r"(b[0]), "r"(b[1]));
}

template<bool RELU, typename OutT>
__global__ __launch_bounds__(256)
void gemm_tc_kernel(const __half* __restrict__ Ab, const float* __restrict__ Bb,
                    const float* __restrict__ biasb, OutT* __restrict__ Cb,
                    int K, int N) {
    extern __shared__ __align__(16) __half smh[];
    const int e  = blockIdx.z;
    const int M  = g_counts[e];
    const int m0 = blockIdx.x * BM;          // m fastest: wave shares B tile in L2
    if (m0 >= M) return;
    const int n0 = blockIdx.y * BN;

    const __half* A    = Ab    + (size_t)e * CAP * K;
    const float*  B    = Bb    + (size_t)e * N   * K;
    const float*  bias = biasb + (size_t)e * N;
    OutT*         C    = Cb    + (size_t)e * CAP * N;

    __half* AsB = smh;               // [2][BM][BKH]
    __half* BsB = smh + 2 * ASZ;     // [2][BN][BKH]

    const int tid  = threadIdx.x;
    const int warp = tid >> 5, lane = tid & 31;
    const int wm   = warp >> 2;
    const int wn   = warp & 3;
    const int grp  = lane >> 2;
    const int tig  = lane & 3;

    // staging coords: row = arow + 32r, col group = aj8 (8 elements)
    const int arow = tid >> 3;
    const int aj8  = (tid & 7) * 8;

    const uint32_t sA = smem_u32(AsB);
    const uint32_t sB = smem_u32(BsB);
    const uint32_t BUFB = (uint32_t)ASZ * 2;   // bytes per buffer
    const uint32_t aLane = (uint32_t)((wm * 64 + (lane & 15)) * (BKH * 2) + (lane >> 4) * 16);
    const uint32_t bLane = (uint32_t)((wn * 32 + ((lane >> 3) & 2) * 4 + (lane & 7)) * (BKH * 2)
                                      + ((lane >> 3) & 1) * 16);

    float acc[4][4][4];
    #pragma unroll
    for (int mi = 0; mi < 4; mi++)
        #pragma unroll
        for (int ni = 0; ni < 4; ni++)
            #pragma unroll
            for (int r = 0; r < 4; r++) acc[mi][ni][r] = 0.f;

    uint4  qa[4];        // A: 8 halves per row-slot
    float4 rb[4][2];     // B: 8 floats per row-slot
    const int T = K / BK;

    // prologue: LDG tile 0, STS into buf 0
    #pragma unroll
    for (int r = 0; r < 4; r++) {
        int gm = m0 + arow + r * 32;
        qa[r] = (gm < M) ? *(const uint4*)&A[(size_t)gm * K + aj8]
                         : make_uint4(0u, 0u, 0u, 0u);
        const float* brow = &B[(size_t)(n0 + arow + r * 32) * K + aj8];
        rb[r][0] = *(const float4*)&brow[0];
        rb[r][1] = *(const float4*)&brow[4];
    }
    #pragma unroll
    for (int r = 0; r < 4; r++) {
        int ro = (arow + r * 32) * BKH + aj8;
        *(uint4*)&AsB[ro] = qa[r];
        *(uint4*)&BsB[ro] = make_uint4(pack_h2(rb[r][0].x, rb[r][0].y),
                                       pack_h2(rb[r][0].z, rb[r][0].w),
                                       pack_h2(rb[r][1].x, rb[r][1].y),
                                       pack_h2(rb[r][1].z, rb[r][1].w));
    }
    __syncthreads();

    for (int t = 0; t < T; t++) {
        const int cur = t & 1, nxt = cur ^ 1;
        const bool more = (t + 1 < T);

        if (more) {
            const int kb = (t + 1) * BK;
            #pragma unroll
            for (int r = 0; r < 4; r++) {
                int gm = m0 + arow + r * 32;
                qa[r] = (gm < M) ? *(const uint4*)&A[(size_t)gm * K + kb + aj8]
                                 : make_uint4(0u, 0u, 0u, 0u);
                const float* brow = &B[(size_t)(n0 + arow + r * 32) * K + kb + aj8];
                rb[r][0] = *(const float4*)&brow[0];
                rb[r][1] = *(const float4*)&brow[4];
            }
        }

        const uint32_t aB = sA + (uint32_t)cur * BUFB + aLane;
        const uint32_t bB = sB + (uint32_t)cur * BUFB + bLane;
        #pragma unroll
        for (int kk = 0; kk < BK; kk += 16) {
            const uint32_t ko = (uint32_t)kk * 2;
            uint32_t af[4][4], bq[2][4];
            #pragma unroll
            for (int mi = 0; mi < 4; mi++)
                ldm_x4(af[mi], aB + ko + (uint32_t)(mi * 16 * BKH * 2));
            #pragma unroll
            for (int p = 0; p < 2; p++)
                ldm_x4(bq[p], bB + ko + (uint32_t)(p * 16 * BKH * 2));
            #pragma unroll
            for (int mi = 0; mi < 4; mi++) {
                #pragma unroll
                for (int p = 0; p < 2; p++) {
                    mma_f16(acc[mi][2 * p + 0], af[mi], &bq[p][0]);
                    mma_f16(acc[mi][2 * p + 1], af[mi], &bq[p][2]);
                }
            }
        }

        if (more) {
            #pragma unroll
            for (int r = 0; r < 4; r++) {
                int ro = (arow + r * 32) * BKH + aj8;
                *(uint4*)&AsB[(uint32_t)nxt * ASZ + ro] = qa[r];
                *(uint4*)&BsB[(uint32_t)nxt * ASZ + ro] =
                    make_uint4(pack_h2(rb[r][0].x, rb[r][0].y),
                               pack_h2(rb[r][0].z, rb[r][0].w),
                               pack_h2(rb[r][1].x, rb[r][1].y),
                               pack_h2(rb[r][1].z, rb[r][1].w));
            }
            __syncthreads();
        }
    }

    // epilogue: bias (+relu); fp16 or fp32 stores
    #pragma unroll
    for (int mi = 0; mi < 4; mi++) {
        int r0 = m0 + wm * 64 + mi * 16 + grp;
        int r1 = r0 + 8;
        #pragma unroll
        for (int ni = 0; ni < 4; ni++) {
            int col = n0 + wn * 32 + ni * 8 + tig * 2;
            float2 bv = *(const float2*)&bias[col];
            if (r0 < M) {
                float ox = acc[mi][ni][0] + bv.x, oy = acc[mi][ni][1] + bv.y;
                if (RELU) { ox = fmaxf(ox, 0.f); oy = fmaxf(oy, 0.f); }
                if constexpr (sizeof(OutT) == 2) {
                    *(uint32_t*)&C[(size_t)r0 * N + col] = pack_h2(ox, oy);
                } else {
                    *(float2*)&C[(size_t)r0 * N + col] = make_float2(ox, oy);
                }
            }
            if (r1 < M) {
                float ox = acc[mi][ni][2] + bv.x, oy = acc[mi][ni][3] + bv.y;
                if (RELU) { ox = fmaxf(ox, 0.f); oy = fmaxf(oy, 0.f); }
                if constexpr (sizeof(OutT) == 2) {
                    *(uint32_t*)&C[(size_t)r1 * N + col] = pack_h2(ox, oy);
                } else {
                    *(float2*)&C[(size_t)r1 * N + col] = make_float2(ox, oy);
                }
            }
        }
    }
}

// ---------------- deterministic weighted combine + counter reset -----------
__global__ void combine_kernel(float* __restrict__ out) {
    int t = blockIdx.x;
    // reset counters for the NEXT launch/replay (combine is the last kernel)
    if (t == 0 && threadIdx.x < N_EXP) g_counts[threadIdx.x] = 0;

    int e0 = g_tok_expert[t * 2 + 0], e1 = g_tok_expert[t * 2 + 1];
    int s0 = g_tok_slot[t * 2 + 0],   s1 = g_tok_slot[t * 2 + 1];
    float w0 = g_tok_weight[t * 2 + 0], w1 = g_tok_weight[t * 2 + 1];
    const float4* r0 = (const float4*)(g_eo + ((size_t)e0 * CAP + s0) * D_MODEL);
    const float4* r1 = (const float4*)(g_eo + ((size_t)e1 * CAP + s1) * D_MODEL);
    float4* o = (float4*)(out + (size_t)t * D_MODEL);
    int i = threadIdx.x;
    float4 a = r0[i], b = r1[i];
    float4 v;
    v.x = w0 * a.x + w1 * b.x;
    v.y = w0 * a.y + w1 * b.y;
    v.z = w0 * a.z + w1 * b.z;
    v.w = w0 * a.w + w1 * b.w;
    o[i] = v;
}

// ---------------- device addresses + prewarm --------------------------------
static __half* p_xg = nullptr;
static __half* p_h  = nullptr;
static float*  p_eo = nullptr;

static struct Prewarm {
    Prewarm() {
        (void)cudaGetSymbolAddress((void**)&p_xg, g_xg);
        (void)cudaGetSymbolAddress((void**)&p_h,  g_h);
        (void)cudaGetSymbolAddress((void**)&p_eo, g_eo);
        (void)cudaFuncSetAttribute(gemm_tc_kernel<true,  __half>,
                                   cudaFuncAttributeMaxDynamicSharedMemorySize, SMEM_BYTES);
        (void)cudaFuncSetAttribute(gemm_tc_kernel<false, float>,
                                   cudaFuncAttributeMaxDynamicSharedMemorySize, SMEM_BYTES);
        // prewarm every kernel pre-baseline (module load, lazy driver pools).
        zero_counts_kernel<<<1, 32>>>();
        routing_kernel<<<1, 256>>>(p_eo, p_eo);
        dim3 g1(1, 1, 1);
        gemm_tc_kernel<true,  __half><<<g1, 256, SMEM_BYTES>>>(p_xg, p_eo, p_eo, p_h, D_MODEL, HIDDEN);
        gemm_tc_kernel<false, float ><<<g1, 256, SMEM_BYTES>>>(p_h, p_eo, p_eo, p_eo, HIDDEN, D_MODEL);
        combine_kernel<<<1, 256>>>(p_eo);
        zero_counts_kernel<<<1, 32>>>();     // counts = 0 for launch #1
        (void)cudaDeviceSynchronize();
    }
} s_prewarm;

// ---------------- launch ----------------------------------------------------
extern "C" void kernel_launch(void* const* d_in, const int* in_sizes, int n_in,
                              void* d_out, int out_size) {
    const float* x      = (const float*)d_in[0];
    const float* gate_w = (const float*)d_in[1];
    const float* w1     = (const float*)d_in[2];
    const float* b1     = (const float*)d_in[3];
    const float* w2     = (const float*)d_in[4];
    const float* b2     = (const float*)d_in[5];
    float* out          = (float*)d_out;

    // counts start at 0 (prewarm for call #1; combine's tail resets each time)
    routing_kernel<<<T_TOK, 256>>>(x, gate_w);

    // fc1 + relu: [count x 1024](fp16) @ [4096 x 1024]^T -> [count x 4096](fp16)
    dim3 g1(CAP / BM, HIDDEN / BN, N_EXP);
    gemm_tc_kernel<true, __half><<<g1, 256, SMEM_BYTES>>>(p_xg, w1, b1, p_h, D_MODEL, HIDDEN);

    // fc2: [count x 4096](fp16) @ [1024 x 4096]^T -> [count x 1024](fp32)
    dim3 g2(CAP / BM, D_MODEL / BN, N_EXP);
    gemm_tc_kernel<false, float><<<g2, 256, SMEM_BYTES>>>(p_h, w2, b2, p_eo, HIDDEN, D_MODEL);

    combine_kernel<<<T_TOK, 256>>>(out);
}

// round 15
// speedup vs baseline: 1.0451x; 1.0451x over previous
#include <cuda_runtime.h>
#include <cuda_fp16.h>
#include <math.h>
#include <stdint.h>

// Problem constants
#define T_TOK   2048
#define D_MODEL 1024
#define N_EXP   8
#define HIDDEN  4096
#define TOPK    2
#define CAP     2048

// ---------------- scratch (device globals; no dynamic allocation) ----------
__device__ int    g_counts[N_EXP];
__device__ int    g_tile1;            // fc1 tile queue
__device__ int    g_tile2;            // fc2 tile queue
__device__ int    g_tok_expert[T_TOK * TOPK];
__device__ int    g_tok_slot[T_TOK * TOPK];
__device__ float  g_tok_weight[T_TOK * TOPK];
__device__ __align__(16) __half g_xg[(size_t)N_EXP * CAP * D_MODEL];  // 32 MB
__device__ __align__(16) __half g_h [(size_t)N_EXP * CAP * HIDDEN];   // 128 MB
__device__ __align__(16) float  g_eo[(size_t)N_EXP * CAP * D_MODEL];  // 64 MB

// ---------------- kernel 0: zero counters (prewarm only) -------------------
__global__ void zero_counts_kernel() {
    if (threadIdx.x < N_EXP) g_counts[threadIdx.x] = 0;
    if (threadIdx.x == 0) { g_tile1 = 0; g_tile2 = 0; }
}

__device__ __forceinline__ uint32_t pack_h2(float x, float y) {
    __half2 h = __floats2half2_rn(x, y);
    return *(uint32_t*)&h;
}
__device__ __forceinline__ uint32_t smem_u32(const void* p) {
    uint32_t a;
    asm("{ .reg .u64 t; cvta.to.shared.u64 t, %1; cvt.u32.u64 %0, t; }" : "=r"(a) : "l"(p));
    return a;
}
__device__ __forceinline__ void ldm_x4(uint32_t* r, uint32_t addr) {
    asm volatile("ldmatrix.sync.aligned.m8n8.x4.shared.b16 {%0,%1,%2,%3}, [%4];"
        : "=r"(r[0]), "=r"(r[1]), "=r"(r[2]), "=r"(r[3]) : "r"(addr));
}

// ---------------- kernel 1: routing (R12-proven: one block per token) ------
__global__ void routing_kernel(const float* __restrict__ x,
                               const float* __restrict__ gate_w) {
    int t = blockIdx.x, tid = threadIdx.x, w = tid >> 5, lane = tid & 31;
    const float* xt = x + (size_t)t * D_MODEL;
    const float* gw = gate_w + (size_t)w * D_MODEL;
    float s = 0.f;
    #pragma unroll 4
    for (int k = lane; k < D_MODEL; k += 32) s += xt[k] * gw[k];
    #pragma unroll
    for (int off = 16; off; off >>= 1) s += __shfl_xor_sync(0xffffffffu, s, off);

    __shared__ float logits[N_EXP];
    __shared__ int   sh_e[TOPK];
    __shared__ int   sh_s[TOPK];
    if (lane == 0) logits[w] = s;
    __syncthreads();

    if (tid == 0) {
        float mx = logits[0];
        #pragma unroll
        for (int i = 1; i < N_EXP; i++) mx = fmaxf(mx, logits[i]);
        float denom = 0.f;
        #pragma unroll
        for (int i = 0; i < N_EXP; i++) denom += expf(logits[i] - mx);
        // top-2 scan; strict '>' keeps lower index on ties (matches jax top_k)
        float v0 = -3.4e38f, v1 = -3.4e38f;
        int   i0 = 0,        i1 = 0;
        #pragma unroll
        for (int i = 0; i < N_EXP; i++) {
            float v = logits[i];
            if (v > v0)      { v1 = v0; i1 = i0; v0 = v; i0 = i; }
            else if (v > v1) { v1 = v;  i1 = i; }
        }
        float p0 = expf(v0 - mx) / denom;
        float p1 = expf(v1 - mx) / denom;
        float inv = 1.f / (p0 + p1);
        p0 *= inv; p1 *= inv;
        int s0 = atomicAdd(&g_counts[i0], 1);
        int s1 = atomicAdd(&g_counts[i1], 1);
        g_tok_expert[t * 2 + 0] = i0;  g_tok_slot[t * 2 + 0] = s0;  g_tok_weight[t * 2 + 0] = p0;
        g_tok_expert[t * 2 + 1] = i1;  g_tok_slot[t * 2 + 1] = s1;  g_tok_weight[t * 2 + 1] = p1;
        sh_e[0] = i0; sh_s[0] = s0; sh_e[1] = i1; sh_s[1] = s1;
    }
    __syncthreads();

    float4 v = ((const float4*)xt)[tid];
    uint2 hv = make_uint2(pack_h2(v.x, v.y), pack_h2(v.z, v.w));
    #pragma unroll
    for (int kk = 0; kk < TOPK; kk++) {
        uint2* dst = (uint2*)(g_xg + ((size_t)sh_e[kk] * CAP + sh_s[kk]) * D_MODEL);
        dst[tid] = hv;
    }
}

// ---------------- persistent fp16 tensor-core grouped NT GEMM --------------
// R12 inner core (proven 333.8us: BK=32, BKH=40, ldmatrix, m-fastest order)
// wrapped in a persistent tile loop: 2xSM CTAs pull tiles from an atomic
// queue -> no wave quantization, no ragged-expert imbalance.
// Tile id order: expert-major, then n, then m (m fastest) => consecutive ids
// share the same B (weight) tile, preserving R12's L2 behavior.

#define BM 128
#define BN 128
#define BK 32
#define BKH 40   // half stride (80 B)
#define GRID_P 296   // 148 SMs x 2 CTAs

__device__ __forceinline__ void mma_f16(float* c, const uint32_t* a, const uint32_t* b) {
    asm volatile(
        "mma.sync.aligned.m16n8k16.row.col.f32.f16.f16.f32 "
        "{%0,%1,%2,%3}, {%4,%5,%6,%7}, {%8,%9}, {%0,%1,%2,%3};"
        : "+f"(c[0]), "+f"(c[1]), "+f"(c[2]), "+f"(c[3])
        : "r"(a[0]), "r"(a[1]), "r"(a[2]), "r"(a[3]), "r"(b[0]), "r"(b[1]));
}

template<bool RELU, typename OutT, int WHICH>
__global__ __launch_bounds__(256)
void gemm_tc_persist(const __half* __restrict__ Ab, const float* __restrict__ Bb,
                     const float* __restrict__ biasb, OutT* __restrict__ Cb,
                     int K, int Ncols) {
    __shared__ __align__(16) __half As[2][BM][BKH];
    __shared__ __align__(16) __half Bs[2][BN][BKH];
    __shared__ int s_mt[N_EXP];
    __shared__ int s_total;
    __shared__ int s_id;

    const int tid  = threadIdx.x;
    const int warp = tid >> 5, lane = tid & 31;
    const int wm   = warp >> 2;
    const int wn   = warp & 3;
    const int grp  = lane >> 2;
    const int tig  = lane & 3;
    const int nt   = Ncols / BN;

    if (tid < N_EXP) s_mt[tid] = (g_counts[tid] + BM - 1) / BM;
    __syncthreads();
    if (tid == 0) {
        int tot = 0;
        #pragma unroll
        for (int i = 0; i < N_EXP; i++) tot += s_mt[i];
        s_total = tot * nt;
    }

    const int arow = tid >> 3;
    const int aj   = (tid & 7) * 4;    // halves
    const int sk   = (tid & 7) * 4;    // floats

    const uint32_t sA = smem_u32(&As[0][0][0]);
    const uint32_t sB = smem_u32(&Bs[0][0][0]);
    const uint32_t ABUF = BM * BKH * 2, BBUF = BN * BKH * 2;
    const uint32_t aLane = (uint32_t)((wm * 64 + (lane & 15)) * (BKH * 2) + (lane >> 4) * 16);
    const uint32_t bLane = (uint32_t)((wn * 32 + ((lane >> 3) & 2) * 4 + (lane & 7)) * (BKH * 2)
                                      + ((lane >> 3) & 1) * 16);
    const int T = K / BK;

    while (true) {
        // grab next tile
        if (tid == 0) s_id = atomicAdd(WHICH == 1 ? &g_tile1 : &g_tile2, 1);
        __syncthreads();
        const int id = s_id;
        if (id >= s_total) break;

        // decode: expert-major, then n, then m (m fastest)
        int rem = id, e = 0;
        while (true) {
            int sz = s_mt[e] * nt;
            if (rem < sz) break;
            rem -= sz;
            e++;
        }
        const int mt = s_mt[e];
        const int m0 = (rem % mt) * BM;
        const int n0 = (rem / mt) * BN;
        const int M  = g_counts[e];

        const __half* A    = Ab    + (size_t)e * CAP * K;
        const float*  B    = Bb    + (size_t)e * Ncols * K;
        const float*  bias = biasb + (size_t)e * Ncols;
        OutT*         C    = Cb    + (size_t)e * CAP * Ncols;

        float acc[4][4][4];
        #pragma unroll
        for (int mi = 0; mi < 4; mi++)
            #pragma unroll
            for (int ni = 0; ni < 4; ni++)
                #pragma unroll
                for (int r = 0; r < 4; r++) acc[mi][ni][r] = 0.f;

        uint2  qa[4];
        float4 rb[4];

        // prologue: LDG tile 0, STS into buf 0
        #pragma unroll
        for (int r = 0; r < 4; r++) {
            int gm = m0 + arow + r * 32;
            qa[r] = (gm < M) ? *(const uint2*)&A[(size_t)gm * K + aj] : make_uint2(0u, 0u);
            rb[r] = *(const float4*)&B[(size_t)(n0 + arow + r * 32) * K + sk];
        }
        #pragma unroll
        for (int r = 0; r < 4; r++) {
            *(uint2*)&As[0][arow + r * 32][aj] = qa[r];
            *(uint2*)&Bs[0][arow + r * 32][sk] =
                make_uint2(pack_h2(rb[r].x, rb[r].y), pack_h2(rb[r].z, rb[r].w));
        }
        __syncthreads();

        for (int t = 0; t < T; t++) {
            const int cur = t & 1, nxt = cur ^ 1;
            const bool more = (t + 1 < T);

            if (more) {
                const int kb = (t + 1) * BK;
                #pragma unroll
                for (int r = 0; r < 4; r++) {
                    int gm = m0 + arow + r * 32;
                    qa[r] = (gm < M) ? *(const uint2*)&A[(size_t)gm * K + kb + aj] : make_uint2(0u, 0u);
                    rb[r] = *(const float4*)&B[(size_t)(n0 + arow + r * 32) * K + kb + sk];
                }
            }

            const uint32_t aB = sA + (uint32_t)cur * ABUF + aLane;
            const uint32_t bB = sB + (uint32_t)cur * BBUF + bLane;
            #pragma unroll
            for (int kk = 0; kk < BK; kk += 16) {
                const uint32_t ko = (uint32_t)kk * 2;
                uint32_t af[4][4], bq[2][4];
                #pragma unroll
                for (int mi = 0; mi < 4; mi++)
                    ldm_x4(af[mi], aB + ko + (uint32_t)(mi * 16 * BKH * 2));
                #pragma unroll
                for (int p = 0; p < 2; p++)
                    ldm_x4(bq[p], bB + ko + (uint32_t)(p * 16 * BKH * 2));
                #pragma unroll
                for (int mi = 0; mi < 4; mi++) {
                    #pragma unroll
                    for (int p = 0; p < 2; p++) {
                        mma_f16(acc[mi][2 * p + 0], af[mi], &bq[p][0]);
                        mma_f16(acc[mi][2 * p + 1], af[mi], &bq[p][2]);
                    }
                }
            }

            if (more) {
                #pragma unroll
                for (int r = 0; r < 4; r++) {
                    *(uint2*)&As[nxt][arow + r * 32][aj] = qa[r];
                    *(uint2*)&Bs[nxt][arow + r * 32][sk] =
                        make_uint2(pack_h2(rb[r].x, rb[r].y), pack_h2(rb[r].z, rb[r].w));
                }
                __syncthreads();
            }
        }

        // epilogue: bias (+relu); fp16 or fp32 stores
        #pragma unroll
        for (int mi = 0; mi < 4; mi++) {
            int r0 = m0 + wm * 64 + mi * 16 + grp;
            int r1 = r0 + 8;
            #pragma unroll
            for (int ni = 0; ni < 4; ni++) {
                int col = n0 + wn * 32 + ni * 8 + tig * 2;
                float2 bv = *(const float2*)&bias[col];
                if (r0 < M) {
                    float ox = acc[mi][ni][0] + bv.x, oy = acc[mi][ni][1] + bv.y;
                    if (RELU) { ox = fmaxf(ox, 0.f); oy = fmaxf(oy, 0.f); }
                    if constexpr (sizeof(OutT) == 2) {
                        *(uint32_t*)&C[(size_t)r0 * Ncols + col] = pack_h2(ox, oy);
                    } else {
                        *(float2*)&C[(size_t)r0 * Ncols + col] = make_float2(ox, oy);
                    }
                }
                if (r1 < M) {
                    float ox = acc[mi][ni][2] + bv.x, oy = acc[mi][ni][3] + bv.y;
                    if (RELU) { ox = fmaxf(ox, 0.f); oy = fmaxf(oy, 0.f); }
                    if constexpr (sizeof(OutT) == 2) {
                        *(uint32_t*)&C[(size_t)r1 * Ncols + col] = pack_h2(ox, oy);
                    } else {
                        *(float2*)&C[(size_t)r1 * Ncols + col] = make_float2(ox, oy);
                    }
                }
            }
        }
        __syncthreads();   // protect smem before next tile's prologue
    }
}

// ---------------- deterministic weighted combine + counter reset -----------
__global__ void combine_kernel(float* __restrict__ out) {
    int t = blockIdx.x;
    // reset all queue/count state for the NEXT launch/replay
    if (t == 0) {
        if (threadIdx.x < N_EXP) g_counts[threadIdx.x] = 0;
        if (threadIdx.x == 32) g_tile1 = 0;
        if (threadIdx.x == 33) g_tile2 = 0;
    }

    int e0 = g_tok_expert[t * 2 + 0], e1 = g_tok_expert[t * 2 + 1];
    int s0 = g_tok_slot[t * 2 + 0],   s1 = g_tok_slot[t * 2 + 1];
    float w0 = g_tok_weight[t * 2 + 0], w1 = g_tok_weight[t * 2 + 1];
    const float4* r0 = (const float4*)(g_eo + ((size_t)e0 * CAP + s0) * D_MODEL);
    const float4* r1 = (const float4*)(g_eo + ((size_t)e1 * CAP + s1) * D_MODEL);
    float4* o = (float4*)(out + (size_t)t * D_MODEL);
    int i = threadIdx.x;
    float4 a = r0[i], b = r1[i];
    float4 v;
    v.x = w0 * a.x + w1 * b.x;
    v.y = w0 * a.y + w1 * b.y;
    v.z = w0 * a.z + w1 * b.z;
    v.w = w0 * a.w + w1 * b.w;
    o[i] = v;
}

// ---------------- device addresses + prewarm --------------------------------
static __half* p_xg = nullptr;
static __half* p_h  = nullptr;
static float*  p_eo = nullptr;

static struct Prewarm {
    Prewarm() {
        (void)cudaGetSymbolAddress((void**)&p_xg, g_xg);
        (void)cudaGetSymbolAddress((void**)&p_h,  g_h);
        (void)cudaGetSymbolAddress((void**)&p_eo, g_eo);
        // prewarm every kernel pre-baseline (module load, lazy driver pools).
        zero_counts_kernel<<<1, 64>>>();
        routing_kernel<<<1, 256>>>(p_eo, p_eo);
        gemm_tc_persist<true,  __half, 1><<<2, 256>>>(p_xg, p_eo, p_eo, p_h, D_MODEL, HIDDEN);
        gemm_tc_persist<false, float,  2><<<2, 256>>>(p_h, p_eo, p_eo, p_eo, HIDDEN, D_MODEL);
        combine_kernel<<<1, 256>>>(p_eo);
        zero_counts_kernel<<<1, 64>>>();     // counts + queues = 0 for launch #1
        (void)cudaDeviceSynchronize();
    }
} s_prewarm;

// ---------------- launch ----------------------------------------------------
extern "C" void kernel_launch(void* const* d_in, const int* in_sizes, int n_in,
                              void* d_out, int out_size) {
    const float* x      = (const float*)d_in[0];
    const float* gate_w = (const float*)d_in[1];
    const float* w1     = (const float*)d_in[2];
    const float* b1     = (const float*)d_in[3];
    const float* w2     = (const float*)d_in[4];
    const float* b2     = (const float*)d_in[5];
    float* out          = (float*)d_out;

    // counts/queues start at 0 (prewarm for call #1; combine tail resets)
    routing_kernel<<<T_TOK, 256>>>(x, gate_w);

    // fc1 + relu: persistent grid, tiles pulled from g_tile1
    gemm_tc_persist<true, __half, 1><<<GRID_P, 256>>>(p_xg, w1, b1, p_h, D_MODEL, HIDDEN);

    // fc2: persistent grid, tiles pulled from g_tile2
    gemm_tc_persist<false, float, 2><<<GRID_P, 256>>>(p_h, w2, b2, p_eo, HIDDEN, D_MODEL);

    combine_kernel<<<T_TOK, 256>>>(out);
}

// round 16
// speedup vs baseline: 1.1352x; 1.0862x over previous
#include <cuda_runtime.h>
#include <cuda_fp16.h>
#include <math.h>
#include <stdint.h>

// Problem constants
#define T_TOK   2048
#define D_MODEL 1024
#define N_EXP   8
#define HIDDEN  4096
#define TOPK    2
#define CAP     2048

// ---------------- scratch (device globals; no dynamic allocation) ----------
__device__ int    g_counts[N_EXP];
__device__ int    g_tok_expert[T_TOK * TOPK];
__device__ int    g_tok_slot[T_TOK * TOPK];
__device__ float  g_tok_weight[T_TOK * TOPK];
__device__ __align__(16) __half g_xg[(size_t)N_EXP * CAP * D_MODEL];  // 32 MB
__device__ __align__(16) __half g_h [(size_t)N_EXP * CAP * HIDDEN];   // 128 MB
__device__ __align__(16) float  g_eo[(size_t)N_EXP * CAP * D_MODEL];  // 64 MB

// ---------------- kernel 0: zero counters (prewarm only) -------------------
__global__ void zero_counts_kernel() {
    if (threadIdx.x < N_EXP) g_counts[threadIdx.x] = 0;
}

__device__ __forceinline__ uint32_t pack_h2(float x, float y) {
    __half2 h = __floats2half2_rn(x, y);
    return *(uint32_t*)&h;
}
__device__ __forceinline__ uint32_t smem_u32(const void* p) {
    uint32_t a;
    asm("{ .reg .u64 t; cvta.to.shared.u64 t, %1; cvt.u32.u64 %0, t; }" : "=r"(a) : "l"(p));
    return a;
}
__device__ __forceinline__ void ldm_x4(uint32_t* r, uint32_t addr) {
    asm volatile("ldmatrix.sync.aligned.m8n8.x4.shared.b16 {%0,%1,%2,%3}, [%4];"
        : "=r"(r[0]), "=r"(r[1]), "=r"(r[2]), "=r"(r[3]) : "r"(addr));
}

// ---------------- kernel 1: routing (R12-proven: one block per token) ------
// No dynamically-indexed local arrays (lmem-pool guard).
__global__ void routing_kernel(const float* __restrict__ x,
                               const float* __restrict__ gate_w) {
    int t = blockIdx.x, tid = threadIdx.x, w = tid >> 5, lane = tid & 31;
    const float* xt = x + (size_t)t * D_MODEL;
    const float* gw = gate_w + (size_t)w * D_MODEL;
    float s = 0.f;
    #pragma unroll 4
    for (int k = lane; k < D_MODEL; k += 32) s += xt[k] * gw[k];
    #pragma unroll
    for (int off = 16; off; off >>= 1) s += __shfl_xor_sync(0xffffffffu, s, off);

    __shared__ float logits[N_EXP];
    __shared__ int   sh_e[TOPK];
    __shared__ int   sh_s[TOPK];
    if (lane == 0) logits[w] = s;
    __syncthreads();

    if (tid == 0) {
        float mx = logits[0];
        #pragma unroll
        for (int i = 1; i < N_EXP; i++) mx = fmaxf(mx, logits[i]);
        float denom = 0.f;
        #pragma unroll
        for (int i = 0; i < N_EXP; i++) denom += expf(logits[i] - mx);
        // top-2 scan; strict '>' keeps lower index on ties (matches jax top_k)
        float v0 = -3.4e38f, v1 = -3.4e38f;
        int   i0 = 0,        i1 = 0;
        #pragma unroll
        for (int i = 0; i < N_EXP; i++) {
            float v = logits[i];
            if (v > v0)      { v1 = v0; i1 = i0; v0 = v; i0 = i; }
            else if (v > v1) { v1 = v;  i1 = i; }
        }
        float p0 = expf(v0 - mx) / denom;
        float p1 = expf(v1 - mx) / denom;
        float inv = 1.f / (p0 + p1);
        p0 *= inv; p1 *= inv;
        int s0 = atomicAdd(&g_counts[i0], 1);
        int s1 = atomicAdd(&g_counts[i1], 1);
        g_tok_expert[t * 2 + 0] = i0;  g_tok_slot[t * 2 + 0] = s0;  g_tok_weight[t * 2 + 0] = p0;
        g_tok_expert[t * 2 + 1] = i1;  g_tok_slot[t * 2 + 1] = s1;  g_tok_weight[t * 2 + 1] = p1;
        sh_e[0] = i0; sh_s[0] = s0; sh_e[1] = i1; sh_s[1] = s1;
    }
    __syncthreads();

    // gather token row (fp32 -> fp16) into both experts' input buffers
    float4 v = ((const float4*)xt)[tid];
    uint2 hv = make_uint2(pack_h2(v.x, v.y), pack_h2(v.z, v.w));
    #pragma unroll
    for (int kk = 0; kk < TOPK; kk++) {
        uint2* dst = (uint2*)(g_xg + ((size_t)sh_e[kk] * CAP + sh_s[kk]) * D_MODEL);
        dst[tid] = hv;
    }
}

// ---------------- fp16 tensor-core grouped NT GEMM (R12 core, proven) ------
// C[m,n] = sum_k A[m,k]*B[n,k] + bias[n]  (optional ReLU)
// mma.sync.m16n8k16; block tile 128x128x32; 8 warps of 64x32; double-buffered
// smem with one sync per K-tile; ldmatrix.x4 fragment loads (80B stride ->
// conflict-free); grid x = m-tile fastest so a wave shares the B (weight)
// tile in L2.

#define BM 128
#define BN 128
#define BK 32
#define BKH 40   // half stride (80 B)

__device__ __forceinline__ void mma_f16(float* c, const uint32_t* a, const uint32_t* b) {
    asm volatile(
        "mma.sync.aligned.m16n8k16.row.col.f32.f16.f16.f32 "
        "{%0,%1,%2,%3}, {%4,%5,%6,%7}, {%8,%9}, {%0,%1,%2,%3};"
        : "+f"(c[0]), "+f"(c[1]), "+f"(c[2]), "+f"(c[3])
        : "r"(a[0]), "r"(a[1]), "r"(a[2]), "r"(a[3]), "r"(b[0]), "r"(b[1]));
}

template<bool RELU, typename OutT>
__global__ __launch_bounds__(256)
void gemm_tc_kernel(const __half* __restrict__ Ab, const float* __restrict__ Bb,
                    const float* __restrict__ biasb, OutT* __restrict__ Cb,
                    int K, int N) {
    const int e  = blockIdx.z;
    const int M  = g_counts[e];
    const int m0 = blockIdx.x * BM;          // m fastest: wave shares B tile in L2
    if (m0 >= M) return;
    const int n0 = blockIdx.y * BN;

    const __half* A    = Ab    + (size_t)e * CAP * K;
    const float*  B    = Bb    + (size_t)e * N   * K;
    const float*  bias = biasb + (size_t)e * N;
    OutT*         C    = Cb    + (size_t)e * CAP * N;

    __shared__ __align__(16) __half As[2][BM][BKH];
    __shared__ __align__(16) __half Bs[2][BN][BKH];

    const int tid  = threadIdx.x;
    const int warp = tid >> 5, lane = tid & 31;
    const int wm   = warp >> 2;
    const int wn   = warp & 3;
    const int grp  = lane >> 2;
    const int tig  = lane & 3;

    const int arow = tid >> 3;
    const int aj   = (tid & 7) * 4;    // halves
    const int sk   = (tid & 7) * 4;    // floats

    const uint32_t sA = smem_u32(&As[0][0][0]);
    const uint32_t sB = smem_u32(&Bs[0][0][0]);
    const uint32_t ABUF = BM * BKH * 2, BBUF = BN * BKH * 2;
    const uint32_t aLane = (uint32_t)((wm * 64 + (lane & 15)) * (BKH * 2) + (lane >> 4) * 16);
    const uint32_t bLane = (uint32_t)((wn * 32 + ((lane >> 3) & 2) * 4 + (lane & 7)) * (BKH * 2)
                                      + ((lane >> 3) & 1) * 16);

    float acc[4][4][4];
    #pragma unroll
    for (int mi = 0; mi < 4; mi++)
        #pragma unroll
        for (int ni = 0; ni < 4; ni++)
            #pragma unroll
            for (int r = 0; r < 4; r++) acc[mi][ni][r] = 0.f;

    uint2  qa[4];
    float4 rb[4];
    const int T = K / BK;

    // prologue: LDG tile 0, STS into buf 0
    #pragma unroll
    for (int r = 0; r < 4; r++) {
        int gm = m0 + arow + r * 32;
        qa[r] = (gm < M) ? *(const uint2*)&A[(size_t)gm * K + aj] : make_uint2(0u, 0u);
        rb[r] = *(const float4*)&B[(size_t)(n0 + arow + r * 32) * K + sk];
    }
    #pragma unroll
    for (int r = 0; r < 4; r++) {
        *(uint2*)&As[0][arow + r * 32][aj] = qa[r];
        *(uint2*)&Bs[0][arow + r * 32][sk] =
            make_uint2(pack_h2(rb[r].x, rb[r].y), pack_h2(rb[r].z, rb[r].w));
    }
    __syncthreads();

    for (int t = 0; t < T; t++) {
        const int cur = t & 1, nxt = cur ^ 1;
        const bool more = (t + 1 < T);

        if (more) {
            const int kb = (t + 1) * BK;
            #pragma unroll
            for (int r = 0; r < 4; r++) {
                int gm = m0 + arow + r * 32;
                qa[r] = (gm < M) ? *(const uint2*)&A[(size_t)gm * K + kb + aj] : make_uint2(0u, 0u);
                rb[r] = *(const float4*)&B[(size_t)(n0 + arow + r * 32) * K + kb + sk];
            }
        }

        const uint32_t aB = sA + (uint32_t)cur * ABUF + aLane;
        const uint32_t bB = sB + (uint32_t)cur * BBUF + bLane;
        #pragma unroll
        for (int kk = 0; kk < BK; kk += 16) {
            const uint32_t ko = (uint32_t)kk * 2;
            uint32_t af[4][4], bq[2][4];
            #pragma unroll
            for (int mi = 0; mi < 4; mi++)
                ldm_x4(af[mi], aB + ko + (uint32_t)(mi * 16 * BKH * 2));
            #pragma unroll
            for (int p = 0; p < 2; p++)
                ldm_x4(bq[p], bB + ko + (uint32_t)(p * 16 * BKH * 2));
            #pragma unroll
            for (int mi = 0; mi < 4; mi++) {
                #pragma unroll
                for (int p = 0; p < 2; p++) {
                    mma_f16(acc[mi][2 * p + 0], af[mi], &bq[p][0]);
                    mma_f16(acc[mi][2 * p + 1], af[mi], &bq[p][2]);
                }
            }
        }

        if (more) {
            #pragma unroll
            for (int r = 0; r < 4; r++) {
                *(uint2*)&As[nxt][arow + r * 32][aj] = qa[r];
                *(uint2*)&Bs[nxt][arow + r * 32][sk] =
                    make_uint2(pack_h2(rb[r].x, rb[r].y), pack_h2(rb[r].z, rb[r].w));
            }
            __syncthreads();
        }
    }

    // epilogue: bias (+relu); fp16 or fp32 stores
    #pragma unroll
    for (int mi = 0; mi < 4; mi++) {
        int r0 = m0 + wm * 64 + mi * 16 + grp;
        int r1 = r0 + 8;
        #pragma unroll
        for (int ni = 0; ni < 4; ni++) {
            int col = n0 + wn * 32 + ni * 8 + tig * 2;
            float2 bv = *(const float2*)&bias[col];
            if (r0 < M) {
                float ox = acc[mi][ni][0] + bv.x, oy = acc[mi][ni][1] + bv.y;
                if (RELU) { ox = fmaxf(ox, 0.f); oy = fmaxf(oy, 0.f); }
                if constexpr (sizeof(OutT) == 2) {
                    *(uint32_t*)&C[(size_t)r0 * N + col] = pack_h2(ox, oy);
                } else {
                    *(float2*)&C[(size_t)r0 * N + col] = make_float2(ox, oy);
                }
            }
            if (r1 < M) {
                float ox = acc[mi][ni][2] + bv.x, oy = acc[mi][ni][3] + bv.y;
                if (RELU) { ox = fmaxf(ox, 0.f); oy = fmaxf(oy, 0.f); }
                if constexpr (sizeof(OutT) == 2) {
                    *(uint32_t*)&C[(size_t)r1 * N + col] = pack_h2(ox, oy);
                } else {
                    *(float2*)&C[(size_t)r1 * N + col] = make_float2(ox, oy);
                }
            }
        }
    }
}

// ---------------- deterministic weighted combine + counter reset -----------
// Counter reset in the tail (validated across graph replays in R13/R15)
// replaces the separate zero_counts launch.
__global__ void combine_kernel(float* __restrict__ out) {
    int t = blockIdx.x;
    if (t == 0 && threadIdx.x < N_EXP) g_counts[threadIdx.x] = 0;

    int e0 = g_tok_expert[t * 2 + 0], e1 = g_tok_expert[t * 2 + 1];
    int s0 = g_tok_slot[t * 2 + 0],   s1 = g_tok_slot[t * 2 + 1];
    float w0 = g_tok_weight[t * 2 + 0], w1 = g_tok_weight[t * 2 + 1];
    const float4* r0 = (const float4*)(g_eo + ((size_t)e0 * CAP + s0) * D_MODEL);
    const float4* r1 = (const float4*)(g_eo + ((size_t)e1 * CAP + s1) * D_MODEL);
    float4* o = (float4*)(out + (size_t)t * D_MODEL);
    int i = threadIdx.x;
    float4 a = r0[i], b = r1[i];
    float4 v;
    v.x = w0 * a.x + w1 * b.x;
    v.y = w0 * a.y + w1 * b.y;
    v.z = w0 * a.z + w1 * b.z;
    v.w = w0 * a.w + w1 * b.w;
    o[i] = v;
}

// ---------------- device addresses + prewarm --------------------------------
// A __device__ symbol used by NAME in host code is the HOST shadow address;
// kernel parameters need the real device address via cudaGetSymbolAddress.
static __half* p_xg = nullptr;
static __half* p_h  = nullptr;
static float*  p_eo = nullptr;

static struct Prewarm {
    Prewarm() {
        (void)cudaGetSymbolAddress((void**)&p_xg, g_xg);
        (void)cudaGetSymbolAddress((void**)&p_h,  g_h);
        (void)cudaGetSymbolAddress((void**)&p_eo, g_eo);
        // prewarm every kernel pre-baseline (module load, lazy driver pools).
        zero_counts_kernel<<<1, 32>>>();
        routing_kernel<<<1, 256>>>(p_eo, p_eo);
        dim3 g1(1, 1, 1);
        gemm_tc_kernel<true,  __half><<<g1, 256>>>(p_xg, p_eo, p_eo, p_h, D_MODEL, HIDDEN);
        gemm_tc_kernel<false, float ><<<g1, 256>>>(p_h, p_eo, p_eo, p_eo, HIDDEN, D_MODEL);
        combine_kernel<<<1, 256>>>(p_eo);
        zero_counts_kernel<<<1, 32>>>();     // counts = 0 for launch #1
        (void)cudaDeviceSynchronize();
    }
} s_prewarm;

// ---------------- launch ----------------------------------------------------
extern "C" void kernel_launch(void* const* d_in, const int* in_sizes, int n_in,
                              void* d_out, int out_size) {
    const float* x      = (const float*)d_in[0];
    const float* gate_w = (const float*)d_in[1];
    const float* w1     = (const float*)d_in[2];
    const float* b1     = (const float*)d_in[3];
    const float* w2     = (const float*)d_in[4];
    const float* b2     = (const float*)d_in[5];
    float* out          = (float*)d_out;

    // counts start at 0 (prewarm seeds call #1; combine's tail resets each
    // launch/replay)
    routing_kernel<<<T_TOK, 256>>>(x, gate_w);

    // fc1 + relu: [count x 1024](fp16) @ [4096 x 1024]^T -> [count x 4096](fp16)
    dim3 g1(CAP / BM, HIDDEN / BN, N_EXP);   // x = m-tile (16), y = n-tile (32)
    gemm_tc_kernel<true, __half><<<g1, 256>>>(p_xg, w1, b1, p_h, D_MODEL, HIDDEN);

    // fc2: [count x 4096](fp16) @ [1024 x 4096]^T -> [count x 1024](fp32)
    dim3 g2(CAP / BM, D_MODEL / BN, N_EXP);  // x = m-tile (16), y = n-tile (8)
    gemm_tc_kernel<false, float><<<g2, 256>>>(p_h, w2, b2, p_eo, HIDDEN, D_MODEL);

    combine_kernel<<<T_TOK, 256>>>(out);
}